// round 6
// baseline (speedup 1.0000x reference)
#include <cuda_runtime.h>
#include <math.h>

#define BATCH 1024
#define SEQT 128
#define HIDDEN 512
#define HH (HIDDEN*HIDDEN)
#define BH (BATCH*HIDDEN)
#define NLAYER 4
#define PRED 10
#define INDIM 6
#define OUTDIM 6
#define NT (BATCH*SEQT)
#define ENC_ELEMS (NT*HIDDEN)

typedef unsigned long long u64;

// ---------------- scratch (device globals; no allocation allowed) ----------------
__device__ float g_h[NLAYER*2*BH];            // encoder hidden ping-pong [layer][parity][B*H]
__device__ float g_hd[2*NLAYER*BH];           // decoder hidden ping-pong [parity][layer][B*H]
__device__ float g_part[4*BH];                // split-K partials
__device__ float g_decout[BATCH*PRED*HIDDEN]; // decoder outputs for FC

// ---------------- f32x2 helpers ----------------
__device__ __forceinline__ u64 ffma2(u64 a, u64 b, u64 c){
    u64 d; asm("fma.rn.f32x2 %0, %1, %2, %3;" : "=l"(d) : "l"(a), "l"(b), "l"(c)); return d;
}
__device__ __forceinline__ u64 dup2(float x){
    u64 d; asm("mov.b64 %0, {%1, %1};" : "=l"(d) : "f"(x)); return d;
}
__device__ __forceinline__ float2 unpk(u64 v){
    float2 r; asm("mov.b64 {%0, %1}, %2;" : "=f"(r.x), "=f"(r.y) : "l"(v)); return r;
}

// ---------------- MUFU-free tanh ----------------
__device__ __forceinline__ float fast_tanh(float x){
    float cx = fminf(fmaxf(x, -9.5f), 9.5f);
    float z  = cx * 2.8853900818f;               // 2x * log2(e)
    float y  = z + 12582912.0f;                  // round to nearest int
    int   n  = __float_as_int(y) - 0x4B400000;
    float f  = z - (y - 12582912.0f);            // [-0.5, 0.5]
    float t = 1.5252733e-05f;
    t = fmaf(t, f, 1.5403530e-04f);
    t = fmaf(t, f, 1.3333558e-03f);
    t = fmaf(t, f, 9.6181291e-03f);
    t = fmaf(t, f, 5.5504109e-02f);
    t = fmaf(t, f, 2.4022651e-01f);
    t = fmaf(t, f, 6.9314718e-01f);
    t = t * f;                                   // 2^f - 1
    float s   = __int_as_float((n + 127) << 23);
    float em1 = fmaf(s, t, s - 1.0f);            // e^{2x} - 1
    float ep1 = em1 + 2.0f;
    float r = __int_as_float(0x7EF311C3 - __float_as_int(ep1));
    r = r * fmaf(-ep1, r, 2.0f);
    r = r * fmaf(-ep1, r, 2.0f);
    r = r * fmaf(-ep1, r, 2.0f);
    return em1 * r;
}

// ---------------- double-buffered dual-source GEMM core ----------------
// acc += sum over passes p of A_p[bm:bm+128, kb:kb+ksize] @ W_p[bn:bn+128, kb:kb+ksize]^T
// 256 threads, 8x8 per thread (f32x2: 8x4 u64 accumulators).
// One __syncthreads per 16-k chunk; gmem prefetch one chunk ahead.
__device__ __forceinline__ void gemm_dual(
    const float* __restrict__ A0, const float* __restrict__ W0,
    const float* __restrict__ A1, const float* __restrict__ W1,
    int npass, int kbase, int cshift /*log2 chunks-per-pass*/,
    int bm, int bn, int tid,
    float (*As)[16][132], float (*Ws)[16][132], u64 (*acc)[4])
{
    int tx = tid & 15, ty = tid >> 4;
    int r0 = tid >> 2, kq = (tid & 3) << 2;
    int cmask = (1 << cshift) - 1;
    int nc = npass << cshift;

    const float* Aarr[2] = {A0, A1};
    const float* Warr[2] = {W0, W1};

    float4 pa0, pa1, pw0, pw1;

    auto LOAD = [&](int c){
        int p  = c >> cshift;
        int k0 = kbase + ((c & cmask) << 4);
        const float* Ab = Aarr[p] + (size_t)(bm + r0)*HIDDEN + k0 + kq;
        const float* Wb = Warr[p] + (size_t)(bn + r0)*HIDDEN + k0 + kq;
        pa0 = *(const float4*)Ab;
        pa1 = *(const float4*)(Ab + 64*HIDDEN);
        pw0 = *(const float4*)Wb;
        pw1 = *(const float4*)(Wb + 64*HIDDEN);
    };
    auto STORE = [&](int b){
        float (*A_)[132] = As[b];
        float (*W_)[132] = Ws[b];
        A_[kq+0][r0]=pa0.x;    A_[kq+1][r0]=pa0.y;    A_[kq+2][r0]=pa0.z;    A_[kq+3][r0]=pa0.w;
        A_[kq+0][r0+64]=pa1.x; A_[kq+1][r0+64]=pa1.y; A_[kq+2][r0+64]=pa1.z; A_[kq+3][r0+64]=pa1.w;
        W_[kq+0][r0]=pw0.x;    W_[kq+1][r0]=pw0.y;    W_[kq+2][r0]=pw0.z;    W_[kq+3][r0]=pw0.w;
        W_[kq+0][r0+64]=pw1.x; W_[kq+1][r0+64]=pw1.y; W_[kq+2][r0+64]=pw1.z; W_[kq+3][r0+64]=pw1.w;
    };

    LOAD(0);
    STORE(0);
    __syncthreads();

    for (int c = 0; c < nc; c++) {
        int buf = c & 1;
        if (c + 1 < nc) LOAD(c + 1);
        const float (*Ab)[132] = As[buf];
        const float (*Wb)[132] = Ws[buf];
        #pragma unroll
        for (int kk = 0; kk < 16; kk++) {
            float a[8];
            *(float4*)&a[0] = *(const float4*)&Ab[kk][ty*8];
            *(float4*)&a[4] = *(const float4*)&Ab[kk][ty*8 + 4];
            ulonglong2 w01 = *(const ulonglong2*)&Wb[kk][tx*8];
            ulonglong2 w23 = *(const ulonglong2*)&Wb[kk][tx*8 + 4];
            #pragma unroll
            for (int i = 0; i < 8; i++) {
                u64 ad = dup2(a[i]);
                acc[i][0] = ffma2(ad, w01.x, acc[i][0]);
                acc[i][1] = ffma2(ad, w01.y, acc[i][1]);
                acc[i][2] = ffma2(ad, w23.x, acc[i][2]);
                acc[i][3] = ffma2(ad, w23.y, acc[i][3]);
            }
        }
        if (c + 1 < nc) STORE((c + 1) & 1);
        __syncthreads();
    }
}

// ---------------- layer-0 projection: [NT,6] @ [512,6]^T + bih0 -> enc_out region ----------------
__global__ void __launch_bounds__(512) proj0_kernel(const float* __restrict__ x,
    const float* __restrict__ W, const float* __restrict__ bias, float* __restrict__ out)
{
    __shared__ float Ws[HIDDEN*INDIM];
    __shared__ float bs[HIDDEN];
    __shared__ float xs[32][INDIM];
    int tid = threadIdx.x;
    for (int i = tid; i < HIDDEN*INDIM; i += 512) Ws[i] = W[i];
    if (tid < HIDDEN) bs[tid] = bias[tid];
    int r0 = blockIdx.x * 32;
    if (tid < 32*INDIM) xs[tid/INDIM][tid%INDIM] = x[(size_t)(r0 + tid/INDIM)*INDIM + tid%INDIM];
    __syncthreads();
    int h = tid;
    #pragma unroll 4
    for (int r = 0; r < 32; r++) {
        float acc = bs[h];
        #pragma unroll
        for (int d = 0; d < INDIM; d++) acc += xs[r][d] * Ws[h*INDIM + d];
        out[(size_t)(r0 + r)*HIDDEN + h] = acc;
    }
}

// ---------------- encoder wavefront superstep ----------------
// blockIdx.z = layer l; computes t = s - l.
// l==0: h0_t = tanh(xw0[:,t,:] + h0_{t-1} @ Whh0^T + bhh0)
// l>=1: hl_t = tanh(h_{l-1,t} @ Wih_l^T + h_{l,t-1} @ Whh_l^T + bih_l + bhh_l)
__global__ void __launch_bounds__(256, 1) wave_step(
    int s,
    const float* __restrict__ eWih, const float* __restrict__ eWhh,
    const float* __restrict__ ebih, const float* __restrict__ ebhh,
    float* __restrict__ hb, float* __restrict__ enc_out)
{
    int l = blockIdx.z;
    int t = s - l;
    if (t < 0 || t >= SEQT) return;
    int p_r = (s + 1) & 1, p_w = s & 1;

    __shared__ __align__(16) float As[2][16][132];
    __shared__ __align__(16) float Ws[2][16][132];
    int tid = threadIdx.x;
    int bm = blockIdx.x * 128, bn = blockIdx.y * 128;
    int tx = tid & 15, ty = tid >> 4;

    u64 acc[8][4];
    #pragma unroll
    for (int i = 0; i < 8; i++)
        #pragma unroll
        for (int j = 0; j < 4; j++) acc[i][j] = 0ull;

    if (l == 0) {
        gemm_dual(hb + (size_t)p_r*BH, eWhh, nullptr, nullptr,
                  1, 0, 5, bm, bn, tid, As, Ws, acc);
    } else {
        gemm_dual(hb + ((size_t)(l-1)*2 + p_r)*BH, eWih + (size_t)(l-1)*HH,
                  hb + ((size_t)l*2 + p_r)*BH,     eWhh + (size_t)l*HH,
                  2, 0, 5, bm, bn, tid, As, Ws, acc);
    }

    int n0 = bn + tx*8;
    float bias8[8];
    #pragma unroll
    for (int j = 0; j < 8; j++) {
        bias8[j] = ebhh[l*HIDDEN + n0 + j];
        if (l > 0) bias8[j] += ebih[l*HIDDEN + n0 + j];
    }
    float* hout = hb + ((size_t)l*2 + p_w)*BH;

    #pragma unroll
    for (int i = 0; i < 8; i++) {
        int m = bm + ty*8 + i;
        float o[8];
        #pragma unroll
        for (int j = 0; j < 4; j++) { float2 v = unpk(acc[i][j]); o[2*j] = v.x; o[2*j+1] = v.y; }
        if (l == 0) {
            const float* xr = enc_out + ((size_t)m*SEQT + t)*HIDDEN + n0;
            #pragma unroll
            for (int j = 0; j < 8; j++) o[j] += xr[j];
        }
        #pragma unroll
        for (int j = 0; j < 8; j++) o[j] = fast_tanh(o[j] + bias8[j]);
        float4* dst = (float4*)(hout + (size_t)m*HIDDEN + n0);
        dst[0] = make_float4(o[0], o[1], o[2], o[3]);
        dst[1] = make_float4(o[4], o[5], o[6], o[7]);
        if (l == 3) {
            float4* d2 = (float4*)(enc_out + ((size_t)m*SEQT + t)*HIDDEN + n0);
            d2[0] = make_float4(o[0], o[1], o[2], o[3]);
            d2[1] = make_float4(o[4], o[5], o[6], o[7]);
        }
    }
}

// ---------------- decoder split-K partial: part[z] = chunk of x@Wih^T + h@Whh^T ----------------
__global__ void __launch_bounds__(256, 1) dec_partial(
    const float* __restrict__ xin, const float* __restrict__ Wih,
    const float* __restrict__ hin, const float* __restrict__ Whh,
    float* __restrict__ part)
{
    __shared__ __align__(16) float As[2][16][132];
    __shared__ __align__(16) float Ws[2][16][132];
    int tid = threadIdx.x;
    int bm = blockIdx.x * 128, bn = blockIdx.y * 128;
    int z = blockIdx.z;
    int tx = tid & 15, ty = tid >> 4;

    u64 acc[8][4];
    #pragma unroll
    for (int i = 0; i < 8; i++)
        #pragma unroll
        for (int j = 0; j < 4; j++) acc[i][j] = 0ull;

    const float* A = (z >> 1) ? hin : xin;
    const float* W = (z >> 1) ? Whh : Wih;
    gemm_dual(A, W, nullptr, nullptr, 1, (z & 1) * 256, 4, bm, bn, tid, As, Ws, acc);

    float* dst = part + (size_t)z*BH;
    #pragma unroll
    for (int i = 0; i < 8; i++) {
        int m = bm + ty*8 + i;
        int n0 = bn + tx*8;
        float o[8];
        #pragma unroll
        for (int j = 0; j < 4; j++) { float2 v = unpk(acc[i][j]); o[2*j] = v.x; o[2*j+1] = v.y; }
        float4* d = (float4*)(dst + (size_t)m*HIDDEN + n0);
        d[0] = make_float4(o[0], o[1], o[2], o[3]);
        d[1] = make_float4(o[4], o[5], o[6], o[7]);
    }
}

// ---------------- decoder reduce: h = tanh(sum parts + bih + bhh) ----------------
__global__ void __launch_bounds__(256) dec_reduce(
    const float* __restrict__ part, const float* __restrict__ bih, const float* __restrict__ bhh,
    float* __restrict__ hout, float* __restrict__ dout)
{
    int e = blockIdx.x * blockDim.x + threadIdx.x;   // float4 index over BH/4
    int n = (e & 127) * 4;
    int m = e >> 7;
    size_t off = (size_t)e * 4;
    float4 s0 = *(const float4*)(part + off);
    float4 s1 = *(const float4*)(part + BH + off);
    float4 s2 = *(const float4*)(part + 2*(size_t)BH + off);
    float4 s3 = *(const float4*)(part + 3*(size_t)BH + off);
    float4 b1 = *(const float4*)(bih + n);
    float4 b2 = *(const float4*)(bhh + n);
    float4 v;
    v.x = fast_tanh(s0.x + s1.x + s2.x + s3.x + b1.x + b2.x);
    v.y = fast_tanh(s0.y + s1.y + s2.y + s3.y + b1.y + b2.y);
    v.z = fast_tanh(s0.z + s1.z + s2.z + s3.z + b1.z + b2.z);
    v.w = fast_tanh(s0.w + s1.w + s2.w + s3.w + b1.w + b2.w);
    *(float4*)(hout + off) = v;
    if (dout) *(float4*)(dout + (size_t)m*PRED*HIDDEN + n) = v;
}

// ---------------- final FC: [B*PRED,512] @ [6,512]^T + b ----------------
__global__ void __launch_bounds__(256) fc_kernel(const float* __restrict__ X,
    const float* __restrict__ W, const float* __restrict__ bias, float* __restrict__ out)
{
    __shared__ float Ws[OUTDIM][HIDDEN];
    int tid = threadIdx.x;
    for (int i = tid; i < OUTDIM*HIDDEN; i += 256) Ws[i/HIDDEN][i%HIDDEN] = W[i];
    __syncthreads();
    int warp = tid >> 5, lane = tid & 31;
    int row = blockIdx.x*8 + warp;
    float s[OUTDIM];
    #pragma unroll
    for (int o = 0; o < OUTDIM; o++) s[o] = 0.f;
    for (int k = lane; k < HIDDEN; k += 32) {
        float xv = X[(size_t)row*HIDDEN + k];
        #pragma unroll
        for (int o = 0; o < OUTDIM; o++) s[o] += xv * Ws[o][k];
    }
    #pragma unroll
    for (int o = 0; o < OUTDIM; o++) {
        #pragma unroll
        for (int off = 16; off; off >>= 1) s[o] += __shfl_down_sync(0xffffffffu, s[o], off);
    }
    if (lane == 0) {
        #pragma unroll
        for (int o = 0; o < OUTDIM; o++) out[(size_t)row*OUTDIM + o] = s[o] + bias[o];
    }
}

extern "C" void kernel_launch(void* const* d_in, const int* in_sizes, int n_in,
                              void* d_out, int out_size)
{
    (void)in_sizes; (void)n_in; (void)out_size;
    const float* x     = (const float*)d_in[0];
    const float* eWih0 = (const float*)d_in[1];
    const float* eWih  = (const float*)d_in[2];
    const float* eWhh  = (const float*)d_in[3];
    const float* ebih  = (const float*)d_in[4];
    const float* ebhh  = (const float*)d_in[5];
    const float* dWih  = (const float*)d_in[6];
    const float* dWhh  = (const float*)d_in[7];
    const float* dbih  = (const float*)d_in[8];
    const float* dbhh  = (const float*)d_in[9];
    const float* fcW   = (const float*)d_in[10];
    const float* fcb   = (const float*)d_in[11];

    float* out = (float*)d_out;
    float* enc_out = out;                             // [B, T, H] (staging for xw0, final enc output)
    float* dec_final = out + (size_t)ENC_ELEMS;       // [B, PRED, OUT]

    float *hb, *hd, *part, *dout;
    cudaGetSymbolAddress((void**)&hb,   g_h);
    cudaGetSymbolAddress((void**)&hd,   g_hd);
    cudaGetSymbolAddress((void**)&part, g_part);
    cudaGetSymbolAddress((void**)&dout, g_decout);

    // zero all encoder hidden ping-pong buffers (initial h_{-1} = 0 for every parity)
    cudaMemsetAsync(hb, 0, (size_t)NLAYER*2*BH*sizeof(float), 0);

    // layer-0 input projection (includes bih0) staged into enc_out
    proj0_kernel<<<NT/32, 512>>>(x, eWih0, ebih, enc_out);

    // encoder wavefront: supersteps s = 0 .. SEQT+NLAYER-2
    dim3 wg(BATCH/128, HIDDEN/128, NLAYER);   // 8 x 4 x 4
    for (int s = 0; s < SEQT + NLAYER - 1; s++)
        wave_step<<<wg, 256>>>(s, eWih, eWhh, ebih, ebhh, hb, enc_out);

    // decoder: 10 steps x 4 layers, split-K partial + reduce
    dim3 dg(BATCH/128, HIDDEN/128, 4);        // 8 x 4 x 4
    for (int p = 0; p < PRED; p++) {
        float* hdcur  = hd + (size_t)(p & 1)*NLAYER*BH;
        float* hdprev = hd + (size_t)((p + 1) & 1)*NLAYER*BH;
        for (int l = 0; l < NLAYER; l++) {
            const float* xin = (l == 0)
                ? ((p == 0) ? hb + ((size_t)3*2 + 0)*BH          // h_{3,T-1} parity (127+3)&1=0
                            : hdprev + (size_t)3*BH)
                : hdcur + (size_t)(l-1)*BH;
            const float* hin = (p == 0)
                ? hb + ((size_t)l*2 + ((127 + l) & 1))*BH        // encoder final hidden of layer l
                : hdprev + (size_t)l*BH;
            dec_partial<<<dg, 256>>>(xin, dWih + (size_t)l*HH, hin, dWhh + (size_t)l*HH, part);
            dec_reduce<<<BH/4/256, 256>>>(part, dbih + l*HIDDEN, dbhh + l*HIDDEN,
                                          hdcur + (size_t)l*BH,
                                          (l == NLAYER-1) ? (dout + (size_t)p*HIDDEN) : nullptr);
        }
    }

    // final FC
    fc_kernel<<<BATCH*PRED/8, 256>>>(dout, fcW, fcb, dec_final);
}

// round 7
// speedup vs baseline: 1.2738x; 1.2738x over previous
#include <cuda_runtime.h>
#include <math.h>

#define BATCH 1024
#define SEQT 128
#define HIDDEN 512
#define HH (HIDDEN*HIDDEN)
#define BH (BATCH*HIDDEN)
#define NLAYER 4
#define PRED 10
#define INDIM 6
#define OUTDIM 6
#define NT (BATCH*SEQT)
#define ENC_ELEMS (NT*HIDDEN)

typedef unsigned long long u64;

// ---------------- scratch (device globals; no allocation allowed) ----------------
__device__ float g_h[NLAYER*2*BH];            // encoder hidden ping-pong [layer][parity][B*H]
__device__ float g_hd[2*NLAYER*BH];           // decoder hidden ping-pong [parity][layer][B*H]
__device__ float g_part[4*BH];                // split-K partials
__device__ float g_decout[BATCH*PRED*HIDDEN]; // decoder outputs for FC

// ---------------- f32x2 helpers ----------------
__device__ __forceinline__ u64 ffma2(u64 a, u64 b, u64 c){
    u64 d; asm("fma.rn.f32x2 %0, %1, %2, %3;" : "=l"(d) : "l"(a), "l"(b), "l"(c)); return d;
}
__device__ __forceinline__ u64 dup2(float x){
    u64 d; asm("mov.b64 %0, {%1, %1};" : "=l"(d) : "f"(x)); return d;
}
__device__ __forceinline__ float2 unpk(u64 v){
    float2 r; asm("mov.b64 {%0, %1}, %2;" : "=f"(r.x), "=f"(r.y) : "l"(v)); return r;
}

// ---------------- MUFU-free tanh ----------------
__device__ __forceinline__ float fast_tanh(float x){
    float cx = fminf(fmaxf(x, -9.5f), 9.5f);
    float z  = cx * 2.8853900818f;               // 2x * log2(e)
    float y  = z + 12582912.0f;                  // round to nearest int
    int   n  = __float_as_int(y) - 0x4B400000;
    float f  = z - (y - 12582912.0f);            // [-0.5, 0.5]
    float t = 1.5252733e-05f;
    t = fmaf(t, f, 1.5403530e-04f);
    t = fmaf(t, f, 1.3333558e-03f);
    t = fmaf(t, f, 9.6181291e-03f);
    t = fmaf(t, f, 5.5504109e-02f);
    t = fmaf(t, f, 2.4022651e-01f);
    t = fmaf(t, f, 6.9314718e-01f);
    t = t * f;                                   // 2^f - 1
    float s   = __int_as_float((n + 127) << 23);
    float em1 = fmaf(s, t, s - 1.0f);            // e^{2x} - 1
    float ep1 = em1 + 2.0f;
    float r = __int_as_float(0x7EF311C3 - __float_as_int(ep1));
    r = r * fmaf(-ep1, r, 2.0f);
    r = r * fmaf(-ep1, r, 2.0f);
    r = r * fmaf(-ep1, r, 2.0f);
    return em1 * r;
}

// ---------------- single-buffer GEMM pass (R4-proven structure) ----------------
// acc += A[bm:bm+128, kb:ke] @ W[bn:bn+128, kb:ke]^T
// 256 threads; per-thread output: rows bm+ty*8..+7, cols {bn+tx*4..+3} u {bn+64+tx*4..+3}.
// W fragment read as two conflict-free 16B LDS (4+4 split); A reads broadcast.
#define STORE_SMEM() do { \
    As[kq+0][r0]=pa0.x;    As[kq+1][r0]=pa0.y;    As[kq+2][r0]=pa0.z;    As[kq+3][r0]=pa0.w; \
    As[kq+0][r0+64]=pa1.x; As[kq+1][r0+64]=pa1.y; As[kq+2][r0+64]=pa1.z; As[kq+3][r0+64]=pa1.w; \
    Ws[kq+0][r0]=pw0.x;    Ws[kq+1][r0]=pw0.y;    Ws[kq+2][r0]=pw0.z;    Ws[kq+3][r0]=pw0.w; \
    Ws[kq+0][r0+64]=pw1.x; Ws[kq+1][r0+64]=pw1.y; Ws[kq+2][r0+64]=pw1.z; Ws[kq+3][r0+64]=pw1.w; \
} while(0)

__device__ __forceinline__ void gemm_pass(
    const float* __restrict__ A, const float* __restrict__ W,
    int kb, int ke, int bm, int bn, int tid,
    float (*As)[132], float (*Ws)[132], u64 (*acc)[4])
{
    int tx = tid & 15, ty = tid >> 4;
    int r0 = tid >> 2, kq = (tid & 3) << 2;
    const float* Ab = A + (size_t)(bm + r0)*HIDDEN + kq;
    const float* Wb = W + (size_t)(bn + r0)*HIDDEN + kq;
    float4 pa0 = *(const float4*)(Ab + kb);
    float4 pa1 = *(const float4*)(Ab + 64*HIDDEN + kb);
    float4 pw0 = *(const float4*)(Wb + kb);
    float4 pw1 = *(const float4*)(Wb + 64*HIDDEN + kb);

    for (int k0 = kb; k0 < ke; k0 += 16) {
        __syncthreads();
        STORE_SMEM();
        __syncthreads();
        if (k0 + 16 < ke) {
            pa0 = *(const float4*)(Ab + k0 + 16);
            pa1 = *(const float4*)(Ab + 64*HIDDEN + k0 + 16);
            pw0 = *(const float4*)(Wb + k0 + 16);
            pw1 = *(const float4*)(Wb + 64*HIDDEN + k0 + 16);
        }
        #pragma unroll
        for (int kk = 0; kk < 16; kk++) {
            float a[8];
            *(float4*)&a[0] = *(const float4*)&As[kk][ty*8];
            *(float4*)&a[4] = *(const float4*)&As[kk][ty*8 + 4];
            ulonglong2 wlo = *(const ulonglong2*)&Ws[kk][tx*4];        // cols tx*4..+3
            ulonglong2 whi = *(const ulonglong2*)&Ws[kk][64 + tx*4];   // cols 64+tx*4..+3
            #pragma unroll
            for (int i = 0; i < 8; i++) {
                u64 ad = dup2(a[i]);
                acc[i][0] = ffma2(ad, wlo.x, acc[i][0]);
                acc[i][1] = ffma2(ad, wlo.y, acc[i][1]);
                acc[i][2] = ffma2(ad, whi.x, acc[i][2]);
                acc[i][3] = ffma2(ad, whi.y, acc[i][3]);
            }
        }
    }
}

// ---------------- layer-0 projection: [NT,6] @ [512,6]^T + bih0 -> enc_out region ----------------
__global__ void __launch_bounds__(512) proj0_kernel(const float* __restrict__ x,
    const float* __restrict__ W, const float* __restrict__ bias, float* __restrict__ out)
{
    __shared__ float Ws[HIDDEN*INDIM];
    __shared__ float bs[HIDDEN];
    __shared__ float xs[32][INDIM];
    int tid = threadIdx.x;
    for (int i = tid; i < HIDDEN*INDIM; i += 512) Ws[i] = W[i];
    if (tid < HIDDEN) bs[tid] = bias[tid];
    int r0 = blockIdx.x * 32;
    if (tid < 32*INDIM) xs[tid/INDIM][tid%INDIM] = x[(size_t)(r0 + tid/INDIM)*INDIM + tid%INDIM];
    __syncthreads();
    int h = tid;
    #pragma unroll 4
    for (int r = 0; r < 32; r++) {
        float acc = bs[h];
        #pragma unroll
        for (int d = 0; d < INDIM; d++) acc += xs[r][d] * Ws[h*INDIM + d];
        out[(size_t)(r0 + r)*HIDDEN + h] = acc;
    }
}

// ---------------- encoder wavefront superstep ----------------
// blockIdx.z = layer l; computes t = s - l.
// l==0: h0_t = tanh(xw0[:,t,:] + h0_{t-1} @ Whh0^T + bhh0)
// l>=1: hl_t = tanh(h_{l-1,t} @ Wih_l^T + h_{l,t-1} @ Whh_l^T + bih_l + bhh_l)
__global__ void __launch_bounds__(256, 1) wave_step(
    int s,
    const float* __restrict__ eWih, const float* __restrict__ eWhh,
    const float* __restrict__ ebih, const float* __restrict__ ebhh,
    float* __restrict__ hb, float* __restrict__ enc_out)
{
    int l = blockIdx.z;
    int t = s - l;
    if (t < 0 || t >= SEQT) return;
    int p_r = (s + 1) & 1, p_w = s & 1;

    __shared__ __align__(16) float As[16][132];
    __shared__ __align__(16) float Ws[16][132];
    int tid = threadIdx.x;
    int bm = blockIdx.x * 128, bn = blockIdx.y * 128;
    int tx = tid & 15, ty = tid >> 4;

    u64 acc[8][4];
    #pragma unroll
    for (int i = 0; i < 8; i++)
        #pragma unroll
        for (int j = 0; j < 4; j++) acc[i][j] = 0ull;

    if (l == 0) {
        gemm_pass(hb + (size_t)p_r*BH, eWhh, 0, HIDDEN, bm, bn, tid, As, Ws, acc);
    } else {
        gemm_pass(hb + ((size_t)(l-1)*2 + p_r)*BH, eWih + (size_t)(l-1)*HH, 0, HIDDEN, bm, bn, tid, As, Ws, acc);
        gemm_pass(hb + ((size_t)l*2 + p_r)*BH,     eWhh + (size_t)l*HH,     0, HIDDEN, bm, bn, tid, As, Ws, acc);
    }

    // 4+4 split column map
    int na = bn + tx*4;          // cols for acc[i][0..1]
    int nb = bn + 64 + tx*4;     // cols for acc[i][2..3]
    float biasA[4], biasB[4];
    #pragma unroll
    for (int j = 0; j < 4; j++) {
        biasA[j] = ebhh[l*HIDDEN + na + j];
        biasB[j] = ebhh[l*HIDDEN + nb + j];
        if (l > 0) {
            biasA[j] += ebih[l*HIDDEN + na + j];
            biasB[j] += ebih[l*HIDDEN + nb + j];
        }
    }
    float* hout = hb + ((size_t)l*2 + p_w)*BH;

    #pragma unroll
    for (int i = 0; i < 8; i++) {
        int m = bm + ty*8 + i;
        float o[8];
        #pragma unroll
        for (int j = 0; j < 4; j++) { float2 v = unpk(acc[i][j]); o[2*j] = v.x; o[2*j+1] = v.y; }
        if (l == 0) {
            const float* xbase = enc_out + ((size_t)m*SEQT + t)*HIDDEN;
            float4 xa = *(const float4*)(xbase + na);
            float4 xb = *(const float4*)(xbase + nb);
            o[0]+=xa.x; o[1]+=xa.y; o[2]+=xa.z; o[3]+=xa.w;
            o[4]+=xb.x; o[5]+=xb.y; o[6]+=xb.z; o[7]+=xb.w;
        }
        #pragma unroll
        for (int j = 0; j < 4; j++) {
            o[j]   = fast_tanh(o[j]   + biasA[j]);
            o[4+j] = fast_tanh(o[4+j] + biasB[j]);
        }
        float4 va = make_float4(o[0], o[1], o[2], o[3]);
        float4 vb = make_float4(o[4], o[5], o[6], o[7]);
        *(float4*)(hout + (size_t)m*HIDDEN + na) = va;
        *(float4*)(hout + (size_t)m*HIDDEN + nb) = vb;
        if (l == 3) {
            float* ob = enc_out + ((size_t)m*SEQT + t)*HIDDEN;
            *(float4*)(ob + na) = va;
            *(float4*)(ob + nb) = vb;
        }
    }
}

// ---------------- decoder split-K partial: part[z] = chunk of x@Wih^T + h@Whh^T ----------------
__global__ void __launch_bounds__(256, 1) dec_partial(
    const float* __restrict__ xin, const float* __restrict__ Wih,
    const float* __restrict__ hin, const float* __restrict__ Whh,
    float* __restrict__ part)
{
    __shared__ __align__(16) float As[16][132];
    __shared__ __align__(16) float Ws[16][132];
    int tid = threadIdx.x;
    int bm = blockIdx.x * 128, bn = blockIdx.y * 128;
    int z = blockIdx.z;
    int tx = tid & 15, ty = tid >> 4;

    u64 acc[8][4];
    #pragma unroll
    for (int i = 0; i < 8; i++)
        #pragma unroll
        for (int j = 0; j < 4; j++) acc[i][j] = 0ull;

    const float* A = (z >> 1) ? hin : xin;
    const float* W = (z >> 1) ? Whh : Wih;
    int kb = (z & 1) * 256;
    gemm_pass(A, W, kb, kb + 256, bm, bn, tid, As, Ws, acc);

    float* dst = part + (size_t)z*BH;
    int na = bn + tx*4, nb = bn + 64 + tx*4;
    #pragma unroll
    for (int i = 0; i < 8; i++) {
        int m = bm + ty*8 + i;
        float o[8];
        #pragma unroll
        for (int j = 0; j < 4; j++) { float2 v = unpk(acc[i][j]); o[2*j] = v.x; o[2*j+1] = v.y; }
        *(float4*)(dst + (size_t)m*HIDDEN + na) = make_float4(o[0], o[1], o[2], o[3]);
        *(float4*)(dst + (size_t)m*HIDDEN + nb) = make_float4(o[4], o[5], o[6], o[7]);
    }
}

// ---------------- decoder reduce: h = tanh(sum parts + bih + bhh) ----------------
__global__ void __launch_bounds__(256) dec_reduce(
    const float* __restrict__ part, const float* __restrict__ bih, const float* __restrict__ bhh,
    float* __restrict__ hout, float* __restrict__ dout)
{
    int e = blockIdx.x * blockDim.x + threadIdx.x;   // float4 index over BH/4
    int n = (e & 127) * 4;
    int m = e >> 7;
    size_t off = (size_t)e * 4;
    float4 s0 = *(const float4*)(part + off);
    float4 s1 = *(const float4*)(part + BH + off);
    float4 s2 = *(const float4*)(part + 2*(size_t)BH + off);
    float4 s3 = *(const float4*)(part + 3*(size_t)BH + off);
    float4 b1 = *(const float4*)(bih + n);
    float4 b2 = *(const float4*)(bhh + n);
    float4 v;
    v.x = fast_tanh(s0.x + s1.x + s2.x + s3.x + b1.x + b2.x);
    v.y = fast_tanh(s0.y + s1.y + s2.y + s3.y + b1.y + b2.y);
    v.z = fast_tanh(s0.z + s1.z + s2.z + s3.z + b1.z + b2.z);
    v.w = fast_tanh(s0.w + s1.w + s2.w + s3.w + b1.w + b2.w);
    *(float4*)(hout + off) = v;
    if (dout) *(float4*)(dout + (size_t)m*PRED*HIDDEN + n) = v;
}

// ---------------- final FC: [B*PRED,512] @ [6,512]^T + b ----------------
__global__ void __launch_bounds__(256) fc_kernel(const float* __restrict__ X,
    const float* __restrict__ W, const float* __restrict__ bias, float* __restrict__ out)
{
    __shared__ float Ws[OUTDIM][HIDDEN];
    int tid = threadIdx.x;
    for (int i = tid; i < OUTDIM*HIDDEN; i += 256) Ws[i/HIDDEN][i%HIDDEN] = W[i];
    __syncthreads();
    int warp = tid >> 5, lane = tid & 31;
    int row = blockIdx.x*8 + warp;
    float s[OUTDIM];
    #pragma unroll
    for (int o = 0; o < OUTDIM; o++) s[o] = 0.f;
    for (int k = lane; k < HIDDEN; k += 32) {
        float xv = X[(size_t)row*HIDDEN + k];
        #pragma unroll
        for (int o = 0; o < OUTDIM; o++) s[o] += xv * Ws[o][k];
    }
    #pragma unroll
    for (int o = 0; o < OUTDIM; o++) {
        #pragma unroll
        for (int off = 16; off; off >>= 1) s[o] += __shfl_down_sync(0xffffffffu, s[o], off);
    }
    if (lane == 0) {
        #pragma unroll
        for (int o = 0; o < OUTDIM; o++) out[(size_t)row*OUTDIM + o] = s[o] + bias[o];
    }
}

extern "C" void kernel_launch(void* const* d_in, const int* in_sizes, int n_in,
                              void* d_out, int out_size)
{
    (void)in_sizes; (void)n_in; (void)out_size;
    const float* x     = (const float*)d_in[0];
    const float* eWih0 = (const float*)d_in[1];
    const float* eWih  = (const float*)d_in[2];
    const float* eWhh  = (const float*)d_in[3];
    const float* ebih  = (const float*)d_in[4];
    const float* ebhh  = (const float*)d_in[5];
    const float* dWih  = (const float*)d_in[6];
    const float* dWhh  = (const float*)d_in[7];
    const float* dbih  = (const float*)d_in[8];
    const float* dbhh  = (const float*)d_in[9];
    const float* fcW   = (const float*)d_in[10];
    const float* fcb   = (const float*)d_in[11];

    float* out = (float*)d_out;
    float* enc_out = out;                             // [B, T, H] (staging for xw0, final enc output)
    float* dec_final = out + (size_t)ENC_ELEMS;       // [B, PRED, OUT]

    float *hb, *hd, *part, *dout;
    cudaGetSymbolAddress((void**)&hb,   g_h);
    cudaGetSymbolAddress((void**)&hd,   g_hd);
    cudaGetSymbolAddress((void**)&part, g_part);
    cudaGetSymbolAddress((void**)&dout, g_decout);

    // zero all encoder hidden ping-pong buffers (initial h_{-1} = 0 for every parity)
    cudaMemsetAsync(hb, 0, (size_t)NLAYER*2*BH*sizeof(float), 0);

    // layer-0 input projection (includes bih0) staged into enc_out
    proj0_kernel<<<NT/32, 512>>>(x, eWih0, ebih, enc_out);

    // encoder wavefront: supersteps s = 0 .. SEQT+NLAYER-2
    dim3 wg(BATCH/128, HIDDEN/128, NLAYER);   // 8 x 4 x 4
    for (int s = 0; s < SEQT + NLAYER - 1; s++)
        wave_step<<<wg, 256>>>(s, eWih, eWhh, ebih, ebhh, hb, enc_out);

    // decoder: 10 steps x 4 layers, split-K partial + reduce
    dim3 dg(BATCH/128, HIDDEN/128, 4);        // 8 x 4 x 4
    for (int p = 0; p < PRED; p++) {
        float* hdcur  = hd + (size_t)(p & 1)*NLAYER*BH;
        float* hdprev = hd + (size_t)((p + 1) & 1)*NLAYER*BH;
        for (int l = 0; l < NLAYER; l++) {
            const float* xin = (l == 0)
                ? ((p == 0) ? hb + ((size_t)3*2 + 0)*BH          // h_{3,T-1} parity (127+3)&1=0
                            : hdprev + (size_t)3*BH)
                : hdcur + (size_t)(l-1)*BH;
            const float* hin = (p == 0)
                ? hb + ((size_t)l*2 + ((127 + l) & 1))*BH        // encoder final hidden of layer l
                : hdprev + (size_t)l*BH;
            dec_partial<<<dg, 256>>>(xin, dWih + (size_t)l*HH, hin, dWhh + (size_t)l*HH, part);
            dec_reduce<<<BH/4/256, 256>>>(part, dbih + l*HIDDEN, dbhh + l*HIDDEN,
                                          hdcur + (size_t)l*BH,
                                          (l == NLAYER-1) ? (dout + (size_t)p*HIDDEN) : nullptr);
        }
    }

    // final FC
    fc_kernel<<<BATCH*PRED/8, 256>>>(dout, fcW, fcb, dec_final);
}

// round 8
// speedup vs baseline: 1.9833x; 1.5570x over previous
#include <cuda_runtime.h>
#include <math.h>

#define BATCH 1024
#define SEQT 128
#define HIDDEN 512
#define HH (HIDDEN*HIDDEN)
#define BH (BATCH*HIDDEN)
#define NLAYER 4
#define PRED 10
#define INDIM 6
#define OUTDIM 6
#define NT (BATCH*SEQT)
#define ENC_ELEMS (NT*HIDDEN)
#define PADK 20

// ---------------- scratch (device globals; no allocation allowed) ----------------
__device__ float g_h[NLAYER*2*BH];            // encoder hidden ping-pong [layer][parity][B*H]
__device__ float g_hd[2*NLAYER*BH];           // decoder hidden ping-pong [parity][layer][B*H]
__device__ float g_part[4*BH];                // split-K partials
__device__ float g_decout[BATCH*PRED*HIDDEN]; // decoder outputs for FC

// ---------------- tf32 helpers ----------------
__device__ __forceinline__ unsigned cvt_tf32(float v){
    unsigned r; asm("cvt.rna.tf32.f32 %0, %1;" : "=r"(r) : "f"(v)); return r;
}
__device__ __forceinline__ void mma_tf32(float* d, const unsigned* a, const unsigned* b){
    asm volatile(
        "mma.sync.aligned.m16n8k8.row.col.f32.tf32.tf32.f32 "
        "{%0,%1,%2,%3}, {%4,%5,%6,%7}, {%8,%9}, {%0,%1,%2,%3};"
        : "+f"(d[0]), "+f"(d[1]), "+f"(d[2]), "+f"(d[3])
        : "r"(a[0]), "r"(a[1]), "r"(a[2]), "r"(a[3]), "r"(b[0]), "r"(b[1]));
}

// ---------------- MUFU-free tanh ----------------
__device__ __forceinline__ float fast_tanh(float x){
    float cx = fminf(fmaxf(x, -9.5f), 9.5f);
    float z  = cx * 2.8853900818f;               // 2x * log2(e)
    float y  = z + 12582912.0f;                  // round to nearest int
    int   n  = __float_as_int(y) - 0x4B400000;
    float f  = z - (y - 12582912.0f);            // [-0.5, 0.5]
    float t = 1.5252733e-05f;
    t = fmaf(t, f, 1.5403530e-04f);
    t = fmaf(t, f, 1.3333558e-03f);
    t = fmaf(t, f, 9.6181291e-03f);
    t = fmaf(t, f, 5.5504109e-02f);
    t = fmaf(t, f, 2.4022651e-01f);
    t = fmaf(t, f, 6.9314718e-01f);
    t = t * f;                                   // 2^f - 1
    float s   = __int_as_float((n + 127) << 23);
    float em1 = fmaf(s, t, s - 1.0f);            // e^{2x} - 1
    float ep1 = em1 + 2.0f;
    float r = __int_as_float(0x7EF311C3 - __float_as_int(ep1));
    r = r * fmaf(-ep1, r, 2.0f);
    r = r * fmaf(-ep1, r, 2.0f);
    r = r * fmaf(-ep1, r, 2.0f);
    return em1 * r;
}

// ---------------- tf32 tensor-core GEMM pass ----------------
// acc += A[bm:bm+128, kb:ke] @ W[bn:bn+128, kb:ke]^T   (both row-major [*, 512])
// 256 threads = 8 warps; warp tile 32(M) x 64(N): 2 m16 tiles x 8 n8 tiles.
// smem: row-major [128][PADK], tf32-rounded; pad 20 makes all fragment LDS conflict-free.
__device__ __forceinline__ void gemm_tf32(
    const float* __restrict__ A, const float* __restrict__ W,
    int kb, int ke, int bm, int bn, int tid,
    unsigned (*As)[PADK], unsigned (*Ws)[PADK], float (*d)[8][4])
{
    int rowL = tid >> 1;              // 0..127
    int koff = (tid & 1) * 8;         // 0 or 8
    int lane = tid & 31;
    int q = lane >> 2, r = lane & 3;
    int wid = tid >> 5;
    int wm = (wid & 3) * 32;
    int wn = (wid >> 2) * 64;

    const float* Ag = A + (size_t)(bm + rowL)*HIDDEN + koff;
    const float* Wg = W + (size_t)(bn + rowL)*HIDDEN + koff;

    float4 a0 = *(const float4*)(Ag + kb);
    float4 a1 = *(const float4*)(Ag + kb + 4);
    float4 w0 = *(const float4*)(Wg + kb);
    float4 w1 = *(const float4*)(Wg + kb + 4);

    for (int k0 = kb; k0 < ke; k0 += 16) {
        __syncthreads();
        As[rowL][koff+0] = cvt_tf32(a0.x); As[rowL][koff+1] = cvt_tf32(a0.y);
        As[rowL][koff+2] = cvt_tf32(a0.z); As[rowL][koff+3] = cvt_tf32(a0.w);
        As[rowL][koff+4] = cvt_tf32(a1.x); As[rowL][koff+5] = cvt_tf32(a1.y);
        As[rowL][koff+6] = cvt_tf32(a1.z); As[rowL][koff+7] = cvt_tf32(a1.w);
        Ws[rowL][koff+0] = cvt_tf32(w0.x); Ws[rowL][koff+1] = cvt_tf32(w0.y);
        Ws[rowL][koff+2] = cvt_tf32(w0.z); Ws[rowL][koff+3] = cvt_tf32(w0.w);
        Ws[rowL][koff+4] = cvt_tf32(w1.x); Ws[rowL][koff+5] = cvt_tf32(w1.y);
        Ws[rowL][koff+6] = cvt_tf32(w1.z); Ws[rowL][koff+7] = cvt_tf32(w1.w);
        __syncthreads();
        if (k0 + 16 < ke) {
            a0 = *(const float4*)(Ag + k0 + 16);
            a1 = *(const float4*)(Ag + k0 + 20);
            w0 = *(const float4*)(Wg + k0 + 16);
            w1 = *(const float4*)(Wg + k0 + 20);
        }
        #pragma unroll
        for (int s8 = 0; s8 < 16; s8 += 8) {
            unsigned bf[8][2];
            #pragma unroll
            for (int j = 0; j < 8; j++) {
                bf[j][0] = Ws[wn + 8*j + q][s8 + r];
                bf[j][1] = Ws[wn + 8*j + q][s8 + 4 + r];
            }
            #pragma unroll
            for (int t = 0; t < 2; t++) {
                unsigned af[4];
                af[0] = As[wm + 16*t + q][s8 + r];
                af[1] = As[wm + 16*t + 8 + q][s8 + r];
                af[2] = As[wm + 16*t + q][s8 + 4 + r];
                af[3] = As[wm + 16*t + 8 + q][s8 + 4 + r];
                #pragma unroll
                for (int j = 0; j < 8; j++)
                    mma_tf32(d[t][j], af, bf[j]);
            }
        }
    }
}

// ---------------- layer-0 projection: [NT,6] @ [512,6]^T + bih0 -> enc_out region ----------------
__global__ void __launch_bounds__(512) proj0_kernel(const float* __restrict__ x,
    const float* __restrict__ W, const float* __restrict__ bias, float* __restrict__ out)
{
    __shared__ float Ws[HIDDEN*INDIM];
    __shared__ float bs[HIDDEN];
    __shared__ float xs[32][INDIM];
    int tid = threadIdx.x;
    for (int i = tid; i < HIDDEN*INDIM; i += 512) Ws[i] = W[i];
    if (tid < HIDDEN) bs[tid] = bias[tid];
    int r0 = blockIdx.x * 32;
    if (tid < 32*INDIM) xs[tid/INDIM][tid%INDIM] = x[(size_t)(r0 + tid/INDIM)*INDIM + tid%INDIM];
    __syncthreads();
    int h = tid;
    #pragma unroll 4
    for (int r = 0; r < 32; r++) {
        float acc = bs[h];
        #pragma unroll
        for (int d = 0; d < INDIM; d++) acc += xs[r][d] * Ws[h*INDIM + d];
        out[(size_t)(r0 + r)*HIDDEN + h] = acc;
    }
}

// ---------------- encoder wavefront superstep (tf32 tensor core) ----------------
// blockIdx.z = layer l; computes ts = s - l.
__global__ void __launch_bounds__(256, 1) wave_step(
    int s,
    const float* __restrict__ eWih, const float* __restrict__ eWhh,
    const float* __restrict__ ebih, const float* __restrict__ ebhh,
    float* __restrict__ hb, float* __restrict__ enc_out)
{
    int l = blockIdx.z;
    int ts = s - l;
    if (ts < 0 || ts >= SEQT) return;
    int p_r = (s + 1) & 1, p_w = s & 1;

    __shared__ __align__(16) unsigned As[128][PADK];
    __shared__ __align__(16) unsigned Ws[128][PADK];
    int tid = threadIdx.x;
    int bm = blockIdx.x * 128, bn = blockIdx.y * 128;

    float d[2][8][4];
    #pragma unroll
    for (int t = 0; t < 2; t++)
        #pragma unroll
        for (int j = 0; j < 8; j++)
            #pragma unroll
            for (int c = 0; c < 4; c++) d[t][j][c] = 0.f;

    if (l == 0) {
        gemm_tf32(hb + (size_t)p_r*BH, eWhh, 0, HIDDEN, bm, bn, tid, As, Ws, d);
    } else {
        gemm_tf32(hb + ((size_t)(l-1)*2 + p_r)*BH, eWih + (size_t)(l-1)*HH, 0, HIDDEN, bm, bn, tid, As, Ws, d);
        gemm_tf32(hb + ((size_t)l*2 + p_r)*BH,     eWhh + (size_t)l*HH,     0, HIDDEN, bm, bn, tid, As, Ws, d);
    }

    int lane = tid & 31;
    int q = lane >> 2, r = lane & 3;
    int wid = tid >> 5;
    int wm = (wid & 3) * 32;
    int wn = (wid >> 2) * 64;
    float* hout = hb + ((size_t)l*2 + p_w)*BH;

    #pragma unroll
    for (int j = 0; j < 8; j++) {
        int c = bn + wn + 8*j + 2*r;
        float b0 = ebhh[l*HIDDEN + c], b1 = ebhh[l*HIDDEN + c + 1];
        if (l > 0) { b0 += ebih[l*HIDDEN + c]; b1 += ebih[l*HIDDEN + c + 1]; }
        #pragma unroll
        for (int t = 0; t < 2; t++) {
            int ra = bm + wm + 16*t + q;
            int rb = ra + 8;
            float v0 = d[t][j][0] + b0, v1 = d[t][j][1] + b1;
            float v2 = d[t][j][2] + b0, v3 = d[t][j][3] + b1;
            if (l == 0) {
                const float* xa = enc_out + ((size_t)ra*SEQT + ts)*HIDDEN + c;
                const float* xb = enc_out + ((size_t)rb*SEQT + ts)*HIDDEN + c;
                float2 pa = *(const float2*)xa;
                float2 pb = *(const float2*)xb;
                v0 += pa.x; v1 += pa.y; v2 += pb.x; v3 += pb.y;
            }
            v0 = fast_tanh(v0); v1 = fast_tanh(v1);
            v2 = fast_tanh(v2); v3 = fast_tanh(v3);
            *(float2*)(hout + (size_t)ra*HIDDEN + c) = make_float2(v0, v1);
            *(float2*)(hout + (size_t)rb*HIDDEN + c) = make_float2(v2, v3);
            if (l == 3) {
                *(float2*)(enc_out + ((size_t)ra*SEQT + ts)*HIDDEN + c) = make_float2(v0, v1);
                *(float2*)(enc_out + ((size_t)rb*SEQT + ts)*HIDDEN + c) = make_float2(v2, v3);
            }
        }
    }
}

// ---------------- decoder split-K partial (tf32): part[z] = chunk of x@Wih^T or h@Whh^T ----------------
__global__ void __launch_bounds__(256, 1) dec_partial(
    const float* __restrict__ xin, const float* __restrict__ Wih,
    const float* __restrict__ hin, const float* __restrict__ Whh,
    float* __restrict__ part)
{
    __shared__ __align__(16) unsigned As[128][PADK];
    __shared__ __align__(16) unsigned Ws[128][PADK];
    int tid = threadIdx.x;
    int bm = blockIdx.x * 128, bn = blockIdx.y * 128;
    int z = blockIdx.z;

    float d[2][8][4];
    #pragma unroll
    for (int t = 0; t < 2; t++)
        #pragma unroll
        for (int j = 0; j < 8; j++)
            #pragma unroll
            for (int c = 0; c < 4; c++) d[t][j][c] = 0.f;

    const float* A = (z >> 1) ? hin : xin;
    const float* W = (z >> 1) ? Whh : Wih;
    int kb = (z & 1) * 256;
    gemm_tf32(A, W, kb, kb + 256, bm, bn, tid, As, Ws, d);

    int lane = tid & 31;
    int q = lane >> 2, r = lane & 3;
    int wid = tid >> 5;
    int wm = (wid & 3) * 32;
    int wn = (wid >> 2) * 64;
    float* dst = part + (size_t)z*BH;

    #pragma unroll
    for (int j = 0; j < 8; j++) {
        int c = bn + wn + 8*j + 2*r;
        #pragma unroll
        for (int t = 0; t < 2; t++) {
            int ra = bm + wm + 16*t + q;
            int rb = ra + 8;
            *(float2*)(dst + (size_t)ra*HIDDEN + c) = make_float2(d[t][j][0], d[t][j][1]);
            *(float2*)(dst + (size_t)rb*HIDDEN + c) = make_float2(d[t][j][2], d[t][j][3]);
        }
    }
}

// ---------------- decoder reduce: h = tanh(sum parts + bih + bhh) ----------------
__global__ void __launch_bounds__(256) dec_reduce(
    const float* __restrict__ part, const float* __restrict__ bih, const float* __restrict__ bhh,
    float* __restrict__ hout, float* __restrict__ dout)
{
    int e = blockIdx.x * blockDim.x + threadIdx.x;   // float4 index over BH/4
    int n = (e & 127) * 4;
    int m = e >> 7;
    size_t off = (size_t)e * 4;
    float4 s0 = *(const float4*)(part + off);
    float4 s1 = *(const float4*)(part + BH + off);
    float4 s2 = *(const float4*)(part + 2*(size_t)BH + off);
    float4 s3 = *(const float4*)(part + 3*(size_t)BH + off);
    float4 b1 = *(const float4*)(bih + n);
    float4 b2 = *(const float4*)(bhh + n);
    float4 v;
    v.x = fast_tanh(s0.x + s1.x + s2.x + s3.x + b1.x + b2.x);
    v.y = fast_tanh(s0.y + s1.y + s2.y + s3.y + b1.y + b2.y);
    v.z = fast_tanh(s0.z + s1.z + s2.z + s3.z + b1.z + b2.z);
    v.w = fast_tanh(s0.w + s1.w + s2.w + s3.w + b1.w + b2.w);
    *(float4*)(hout + off) = v;
    if (dout) *(float4*)(dout + (size_t)m*PRED*HIDDEN + n) = v;
}

// ---------------- final FC: [B*PRED,512] @ [6,512]^T + b ----------------
__global__ void __launch_bounds__(256) fc_kernel(const float* __restrict__ X,
    const float* __restrict__ W, const float* __restrict__ bias, float* __restrict__ out)
{
    __shared__ float Ws[OUTDIM][HIDDEN];
    int tid = threadIdx.x;
    for (int i = tid; i < OUTDIM*HIDDEN; i += 256) Ws[i/HIDDEN][i%HIDDEN] = W[i];
    __syncthreads();
    int warp = tid >> 5, lane = tid & 31;
    int row = blockIdx.x*8 + warp;
    float s[OUTDIM];
    #pragma unroll
    for (int o = 0; o < OUTDIM; o++) s[o] = 0.f;
    for (int k = lane; k < HIDDEN; k += 32) {
        float xv = X[(size_t)row*HIDDEN + k];
        #pragma unroll
        for (int o = 0; o < OUTDIM; o++) s[o] += xv * Ws[o][k];
    }
    #pragma unroll
    for (int o = 0; o < OUTDIM; o++) {
        #pragma unroll
        for (int off = 16; off; off >>= 1) s[o] += __shfl_down_sync(0xffffffffu, s[o], off);
    }
    if (lane == 0) {
        #pragma unroll
        for (int o = 0; o < OUTDIM; o++) out[(size_t)row*OUTDIM + o] = s[o] + bias[o];
    }
}

extern "C" void kernel_launch(void* const* d_in, const int* in_sizes, int n_in,
                              void* d_out, int out_size)
{
    (void)in_sizes; (void)n_in; (void)out_size;
    const float* x     = (const float*)d_in[0];
    const float* eWih0 = (const float*)d_in[1];
    const float* eWih  = (const float*)d_in[2];
    const float* eWhh  = (const float*)d_in[3];
    const float* ebih  = (const float*)d_in[4];
    const float* ebhh  = (const float*)d_in[5];
    const float* dWih  = (const float*)d_in[6];
    const float* dWhh  = (const float*)d_in[7];
    const float* dbih  = (const float*)d_in[8];
    const float* dbhh  = (const float*)d_in[9];
    const float* fcW   = (const float*)d_in[10];
    const float* fcb   = (const float*)d_in[11];

    float* out = (float*)d_out;
    float* enc_out = out;                             // [B, T, H] (staging for xw0, final enc output)
    float* dec_final = out + (size_t)ENC_ELEMS;       // [B, PRED, OUT]

    float *hb, *hd, *part, *dout;
    cudaGetSymbolAddress((void**)&hb,   g_h);
    cudaGetSymbolAddress((void**)&hd,   g_hd);
    cudaGetSymbolAddress((void**)&part, g_part);
    cudaGetSymbolAddress((void**)&dout, g_decout);

    // zero all encoder hidden ping-pong buffers (initial h_{-1} = 0 for every parity)
    cudaMemsetAsync(hb, 0, (size_t)NLAYER*2*BH*sizeof(float), 0);

    // layer-0 input projection (includes bih0) staged into enc_out
    proj0_kernel<<<NT/32, 512>>>(x, eWih0, ebih, enc_out);

    // encoder wavefront: supersteps s = 0 .. SEQT+NLAYER-2
    dim3 wg(BATCH/128, HIDDEN/128, NLAYER);   // 8 x 4 x 4
    for (int s = 0; s < SEQT + NLAYER - 1; s++)
        wave_step<<<wg, 256>>>(s, eWih, eWhh, ebih, ebhh, hb, enc_out);

    // decoder: 10 steps x 4 layers, split-K partial + reduce
    dim3 dg(BATCH/128, HIDDEN/128, 4);        // 8 x 4 x 4
    for (int p = 0; p < PRED; p++) {
        float* hdcur  = hd + (size_t)(p & 1)*NLAYER*BH;
        float* hdprev = hd + (size_t)((p + 1) & 1)*NLAYER*BH;
        for (int l = 0; l < NLAYER; l++) {
            const float* xin = (l == 0)
                ? ((p == 0) ? hb + ((size_t)3*2 + 0)*BH          // h_{3,T-1} parity (127+3)&1=0
                            : hdprev + (size_t)3*BH)
                : hdcur + (size_t)(l-1)*BH;
            const float* hin = (p == 0)
                ? hb + ((size_t)l*2 + ((127 + l) & 1))*BH        // encoder final hidden of layer l
                : hdprev + (size_t)l*BH;
            dec_partial<<<dg, 256>>>(xin, dWih + (size_t)l*HH, hin, dWhh + (size_t)l*HH, part);
            dec_reduce<<<BH/4/256, 256>>>(part, dbih + l*HIDDEN, dbhh + l*HIDDEN,
                                          hdcur + (size_t)l*BH,
                                          (l == NLAYER-1) ? (dout + (size_t)p*HIDDEN) : nullptr);
        }
    }

    // final FC
    fc_kernel<<<BATCH*PRED/8, 256>>>(dout, fcW, fcb, dec_final);
}

// round 9
// speedup vs baseline: 2.2522x; 1.1356x over previous
#include <cuda_runtime.h>
#include <math.h>

#define BATCH 1024
#define SEQT 128
#define HIDDEN 512
#define HH (HIDDEN*HIDDEN)
#define BH (BATCH*HIDDEN)
#define NLAYER 4
#define PRED 10
#define INDIM 6
#define OUTDIM 6
#define NT (BATCH*SEQT)
#define ENC_ELEMS (NT*HIDDEN)
#define PADK 20

// ---------------- scratch (device globals; no allocation allowed) ----------------
__device__ float g_h[NLAYER*2*BH];            // encoder hidden ping-pong [layer][parity][B*H]
__device__ float g_hd[2*NLAYER*BH];           // decoder hidden ping-pong [parity][layer][B*H]
__device__ float g_part[4*BH];                // split-K partials
__device__ float g_decout[BATCH*PRED*HIDDEN]; // decoder outputs for FC

// ---------------- tf32 helpers ----------------
__device__ __forceinline__ unsigned cvt_tf32(float v){
    unsigned r; asm("cvt.rna.tf32.f32 %0, %1;" : "=r"(r) : "f"(v)); return r;
}
__device__ __forceinline__ void mma_tf32(float* d, const unsigned* a, const unsigned* b){
    asm volatile(
        "mma.sync.aligned.m16n8k8.row.col.f32.tf32.tf32.f32 "
        "{%0,%1,%2,%3}, {%4,%5,%6,%7}, {%8,%9}, {%0,%1,%2,%3};"
        : "+f"(d[0]), "+f"(d[1]), "+f"(d[2]), "+f"(d[3])
        : "r"(a[0]), "r"(a[1]), "r"(a[2]), "r"(a[3]), "r"(b[0]), "r"(b[1]));
}

// ---------------- MUFU-free tanh ----------------
__device__ __forceinline__ float fast_tanh(float x){
    float cx = fminf(fmaxf(x, -9.5f), 9.5f);
    float z  = cx * 2.8853900818f;               // 2x * log2(e)
    float y  = z + 12582912.0f;                  // round to nearest int
    int   n  = __float_as_int(y) - 0x4B400000;
    float f  = z - (y - 12582912.0f);            // [-0.5, 0.5]
    float t = 1.5252733e-05f;
    t = fmaf(t, f, 1.5403530e-04f);
    t = fmaf(t, f, 1.3333558e-03f);
    t = fmaf(t, f, 9.6181291e-03f);
    t = fmaf(t, f, 5.5504109e-02f);
    t = fmaf(t, f, 2.4022651e-01f);
    t = fmaf(t, f, 6.9314718e-01f);
    t = t * f;                                   // 2^f - 1
    float s   = __int_as_float((n + 127) << 23);
    float em1 = fmaf(s, t, s - 1.0f);            // e^{2x} - 1
    float ep1 = em1 + 2.0f;
    float r = __int_as_float(0x7EF311C3 - __float_as_int(ep1));
    r = r * fmaf(-ep1, r, 2.0f);
    r = r * fmaf(-ep1, r, 2.0f);
    r = r * fmaf(-ep1, r, 2.0f);
    return em1 * r;
}

// ---------------- tf32 tensor-core GEMM pass (pipelined) ----------------
// acc += A[bm:bm+128, kb:ke] @ W[bn:bn+128, kb:ke]^T   (both row-major [*, 512])
// 256 threads = 8 warps; warp tile 32(M) x 64(N): 2 m16 tiles x 8 n8 tiles.
// Per chunk: LDG c+1 -> 48 frag LDS (both k8 halves) -> sync -> MMA h0 -> STS c+1 -> MMA h1 -> sync.
// MMAs run with zero smem dependence; STS/gmem latency hidden behind MMA batches.
__device__ __forceinline__ void gemm_tf32(
    const float* __restrict__ A, const float* __restrict__ W,
    int kb, int ke, int bm, int bn, int tid,
    unsigned (*As)[PADK], unsigned (*Ws)[PADK], float (*d)[8][4])
{
    int rowL = tid >> 1;              // 0..127
    int koff = (tid & 1) * 8;         // 0 or 8
    int lane = tid & 31;
    int q = lane >> 2, r = lane & 3;
    int wid = tid >> 5;
    int wm = (wid & 3) * 32;
    int wn = (wid >> 2) * 64;

    const float* Ag = A + (size_t)(bm + rowL)*HIDDEN + koff;
    const float* Wg = W + (size_t)(bn + rowL)*HIDDEN + koff;

    float4 a0 = *(const float4*)(Ag + kb);
    float4 a1 = *(const float4*)(Ag + kb + 4);
    float4 w0 = *(const float4*)(Wg + kb);
    float4 w1 = *(const float4*)(Wg + kb + 4);

#define STS_CHUNK() do { \
    As[rowL][koff+0]=cvt_tf32(a0.x); As[rowL][koff+1]=cvt_tf32(a0.y); \
    As[rowL][koff+2]=cvt_tf32(a0.z); As[rowL][koff+3]=cvt_tf32(a0.w); \
    As[rowL][koff+4]=cvt_tf32(a1.x); As[rowL][koff+5]=cvt_tf32(a1.y); \
    As[rowL][koff+6]=cvt_tf32(a1.z); As[rowL][koff+7]=cvt_tf32(a1.w); \
    Ws[rowL][koff+0]=cvt_tf32(w0.x); Ws[rowL][koff+1]=cvt_tf32(w0.y); \
    Ws[rowL][koff+2]=cvt_tf32(w0.z); Ws[rowL][koff+3]=cvt_tf32(w0.w); \
    Ws[rowL][koff+4]=cvt_tf32(w1.x); Ws[rowL][koff+5]=cvt_tf32(w1.y); \
    Ws[rowL][koff+6]=cvt_tf32(w1.z); Ws[rowL][koff+7]=cvt_tf32(w1.w); \
} while(0)

    STS_CHUNK();
    __syncthreads();

    for (int k0 = kb; k0 < ke; k0 += 16) {
        bool more = (k0 + 16 < ke);
        if (more) {                     // issue gmem prefetch for chunk c+1 early
            a0 = *(const float4*)(Ag + k0 + 16);
            a1 = *(const float4*)(Ag + k0 + 20);
            w0 = *(const float4*)(Wg + k0 + 16);
            w1 = *(const float4*)(Wg + k0 + 20);
        }
        // load ALL fragments of current chunk into registers (both k8 halves)
        unsigned bf[2][8][2], af[2][2][4];
        #pragma unroll
        for (int h = 0; h < 2; h++) {
            int s8 = h * 8;
            #pragma unroll
            for (int j = 0; j < 8; j++) {
                bf[h][j][0] = Ws[wn + 8*j + q][s8 + r];
                bf[h][j][1] = Ws[wn + 8*j + q][s8 + 4 + r];
            }
            #pragma unroll
            for (int t = 0; t < 2; t++) {
                af[h][t][0] = As[wm + 16*t + q][s8 + r];
                af[h][t][1] = As[wm + 16*t + 8 + q][s8 + r];
                af[h][t][2] = As[wm + 16*t + q][s8 + 4 + r];
                af[h][t][3] = As[wm + 16*t + 8 + q][s8 + 4 + r];
            }
        }
        __syncthreads();                // all warps done reading smem
        #pragma unroll
        for (int t = 0; t < 2; t++)     // MMA half 0 — overlaps peers' STS
            #pragma unroll
            for (int j = 0; j < 8; j++)
                mma_tf32(d[t][j], af[0][t], bf[0][j]);
        if (more) STS_CHUNK();          // refill smem while tensor pipe busy
        #pragma unroll
        for (int t = 0; t < 2; t++)     // MMA half 1
            #pragma unroll
            for (int j = 0; j < 8; j++)
                mma_tf32(d[t][j], af[1][t], bf[1][j]);
        __syncthreads();                // STS visible before next frag loads
    }
#undef STS_CHUNK
}

// ---------------- layer-0 projection: [NT,6] @ [512,6]^T + bih0 -> enc_out region ----------------
__global__ void __launch_bounds__(512) proj0_kernel(const float* __restrict__ x,
    const float* __restrict__ W, const float* __restrict__ bias, float* __restrict__ out)
{
    __shared__ float Ws[HIDDEN*INDIM];
    __shared__ float bs[HIDDEN];
    __shared__ float xs[32][INDIM];
    int tid = threadIdx.x;
    for (int i = tid; i < HIDDEN*INDIM; i += 512) Ws[i] = W[i];
    if (tid < HIDDEN) bs[tid] = bias[tid];
    int r0 = blockIdx.x * 32;
    if (tid < 32*INDIM) xs[tid/INDIM][tid%INDIM] = x[(size_t)(r0 + tid/INDIM)*INDIM + tid%INDIM];
    __syncthreads();
    int h = tid;
    #pragma unroll 4
    for (int r = 0; r < 32; r++) {
        float acc = bs[h];
        #pragma unroll
        for (int d = 0; d < INDIM; d++) acc += xs[r][d] * Ws[h*INDIM + d];
        out[(size_t)(r0 + r)*HIDDEN + h] = acc;
    }
}

// ---------------- encoder wavefront superstep (tf32 tensor core) ----------------
// blockIdx.z = layer l; computes ts = s - l.
__global__ void __launch_bounds__(256, 1) wave_step(
    int s,
    const float* __restrict__ eWih, const float* __restrict__ eWhh,
    const float* __restrict__ ebih, const float* __restrict__ ebhh,
    float* __restrict__ hb, float* __restrict__ enc_out)
{
    int l = blockIdx.z;
    int ts = s - l;
    if (ts < 0 || ts >= SEQT) return;
    int p_r = (s + 1) & 1, p_w = s & 1;

    __shared__ __align__(16) unsigned As[128][PADK];
    __shared__ __align__(16) unsigned Ws[128][PADK];
    int tid = threadIdx.x;
    int bm = blockIdx.x * 128, bn = blockIdx.y * 128;

    float d[2][8][4];
    #pragma unroll
    for (int t = 0; t < 2; t++)
        #pragma unroll
        for (int j = 0; j < 8; j++)
            #pragma unroll
            for (int c = 0; c < 4; c++) d[t][j][c] = 0.f;

    if (l == 0) {
        gemm_tf32(hb + (size_t)p_r*BH, eWhh, 0, HIDDEN, bm, bn, tid, As, Ws, d);
    } else {
        gemm_tf32(hb + ((size_t)(l-1)*2 + p_r)*BH, eWih + (size_t)(l-1)*HH, 0, HIDDEN, bm, bn, tid, As, Ws, d);
        gemm_tf32(hb + ((size_t)l*2 + p_r)*BH,     eWhh + (size_t)l*HH,     0, HIDDEN, bm, bn, tid, As, Ws, d);
    }

    int lane = tid & 31;
    int q = lane >> 2, r = lane & 3;
    int wid = tid >> 5;
    int wm = (wid & 3) * 32;
    int wn = (wid >> 2) * 64;
    float* hout = hb + ((size_t)l*2 + p_w)*BH;

    #pragma unroll
    for (int j = 0; j < 8; j++) {
        int c = bn + wn + 8*j + 2*r;
        float b0 = ebhh[l*HIDDEN + c], b1 = ebhh[l*HIDDEN + c + 1];
        if (l > 0) { b0 += ebih[l*HIDDEN + c]; b1 += ebih[l*HIDDEN + c + 1]; }
        #pragma unroll
        for (int t = 0; t < 2; t++) {
            int ra = bm + wm + 16*t + q;
            int rb = ra + 8;
            float v0 = d[t][j][0] + b0, v1 = d[t][j][1] + b1;
            float v2 = d[t][j][2] + b0, v3 = d[t][j][3] + b1;
            if (l == 0) {
                const float* xa = enc_out + ((size_t)ra*SEQT + ts)*HIDDEN + c;
                const float* xb = enc_out + ((size_t)rb*SEQT + ts)*HIDDEN + c;
                float2 pa = *(const float2*)xa;
                float2 pb = *(const float2*)xb;
                v0 += pa.x; v1 += pa.y; v2 += pb.x; v3 += pb.y;
            }
            v0 = fast_tanh(v0); v1 = fast_tanh(v1);
            v2 = fast_tanh(v2); v3 = fast_tanh(v3);
            *(float2*)(hout + (size_t)ra*HIDDEN + c) = make_float2(v0, v1);
            *(float2*)(hout + (size_t)rb*HIDDEN + c) = make_float2(v2, v3);
            if (l == 3) {
                *(float2*)(enc_out + ((size_t)ra*SEQT + ts)*HIDDEN + c) = make_float2(v0, v1);
                *(float2*)(enc_out + ((size_t)rb*SEQT + ts)*HIDDEN + c) = make_float2(v2, v3);
            }
        }
    }
}

// ---------------- decoder split-K partial (tf32): part[z] = chunk of x@Wih^T or h@Whh^T ----------------
__global__ void __launch_bounds__(256, 1) dec_partial(
    const float* __restrict__ xin, const float* __restrict__ Wih,
    const float* __restrict__ hin, const float* __restrict__ Whh,
    float* __restrict__ part)
{
    __shared__ __align__(16) unsigned As[128][PADK];
    __shared__ __align__(16) unsigned Ws[128][PADK];
    int tid = threadIdx.x;
    int bm = blockIdx.x * 128, bn = blockIdx.y * 128;
    int z = blockIdx.z;

    float d[2][8][4];
    #pragma unroll
    for (int t = 0; t < 2; t++)
        #pragma unroll
        for (int j = 0; j < 8; j++)
            #pragma unroll
            for (int c = 0; c < 4; c++) d[t][j][c] = 0.f;

    const float* A = (z >> 1) ? hin : xin;
    const float* W = (z >> 1) ? Whh : Wih;
    int kb = (z & 1) * 256;
    gemm_tf32(A, W, kb, kb + 256, bm, bn, tid, As, Ws, d);

    int lane = tid & 31;
    int q = lane >> 2, r = lane & 3;
    int wid = tid >> 5;
    int wm = (wid & 3) * 32;
    int wn = (wid >> 2) * 64;
    float* dst = part + (size_t)z*BH;

    #pragma unroll
    for (int j = 0; j < 8; j++) {
        int c = bn + wn + 8*j + 2*r;
        #pragma unroll
        for (int t = 0; t < 2; t++) {
            int ra = bm + wm + 16*t + q;
            int rb = ra + 8;
            *(float2*)(dst + (size_t)ra*HIDDEN + c) = make_float2(d[t][j][0], d[t][j][1]);
            *(float2*)(dst + (size_t)rb*HIDDEN + c) = make_float2(d[t][j][2], d[t][j][3]);
        }
    }
}

// ---------------- decoder reduce: h = tanh(sum parts + bih + bhh) ----------------
__global__ void __launch_bounds__(256) dec_reduce(
    const float* __restrict__ part, const float* __restrict__ bih, const float* __restrict__ bhh,
    float* __restrict__ hout, float* __restrict__ dout)
{
    int e = blockIdx.x * blockDim.x + threadIdx.x;   // float4 index over BH/4
    int n = (e & 127) * 4;
    int m = e >> 7;
    size_t off = (size_t)e * 4;
    float4 s0 = *(const float4*)(part + off);
    float4 s1 = *(const float4*)(part + BH + off);
    float4 s2 = *(const float4*)(part + 2*(size_t)BH + off);
    float4 s3 = *(const float4*)(part + 3*(size_t)BH + off);
    float4 b1 = *(const float4*)(bih + n);
    float4 b2 = *(const float4*)(bhh + n);
    float4 v;
    v.x = fast_tanh(s0.x + s1.x + s2.x + s3.x + b1.x + b2.x);
    v.y = fast_tanh(s0.y + s1.y + s2.y + s3.y + b1.y + b2.y);
    v.z = fast_tanh(s0.z + s1.z + s2.z + s3.z + b1.z + b2.z);
    v.w = fast_tanh(s0.w + s1.w + s2.w + s3.w + b1.w + b2.w);
    *(float4*)(hout + off) = v;
    if (dout) *(float4*)(dout + (size_t)m*PRED*HIDDEN + n) = v;
}

// ---------------- final FC: [B*PRED,512] @ [6,512]^T + b ----------------
__global__ void __launch_bounds__(256) fc_kernel(const float* __restrict__ X,
    const float* __restrict__ W, const float* __restrict__ bias, float* __restrict__ out)
{
    __shared__ float Ws[OUTDIM][HIDDEN];
    int tid = threadIdx.x;
    for (int i = tid; i < OUTDIM*HIDDEN; i += 256) Ws[i/HIDDEN][i%HIDDEN] = W[i];
    __syncthreads();
    int warp = tid >> 5, lane = tid & 31;
    int row = blockIdx.x*8 + warp;
    float s[OUTDIM];
    #pragma unroll
    for (int o = 0; o < OUTDIM; o++) s[o] = 0.f;
    for (int k = lane; k < HIDDEN; k += 32) {
        float xv = X[(size_t)row*HIDDEN + k];
        #pragma unroll
        for (int o = 0; o < OUTDIM; o++) s[o] += xv * Ws[o][k];
    }
    #pragma unroll
    for (int o = 0; o < OUTDIM; o++) {
        #pragma unroll
        for (int off = 16; off; off >>= 1) s[o] += __shfl_down_sync(0xffffffffu, s[o], off);
    }
    if (lane == 0) {
        #pragma unroll
        for (int o = 0; o < OUTDIM; o++) out[(size_t)row*OUTDIM + o] = s[o] + bias[o];
    }
}

extern "C" void kernel_launch(void* const* d_in, const int* in_sizes, int n_in,
                              void* d_out, int out_size)
{
    (void)in_sizes; (void)n_in; (void)out_size;
    const float* x     = (const float*)d_in[0];
    const float* eWih0 = (const float*)d_in[1];
    const float* eWih  = (const float*)d_in[2];
    const float* eWhh  = (const float*)d_in[3];
    const float* ebih  = (const float*)d_in[4];
    const float* ebhh  = (const float*)d_in[5];
    const float* dWih  = (const float*)d_in[6];
    const float* dWhh  = (const float*)d_in[7];
    const float* dbih  = (const float*)d_in[8];
    const float* dbhh  = (const float*)d_in[9];
    const float* fcW   = (const float*)d_in[10];
    const float* fcb   = (const float*)d_in[11];

    float* out = (float*)d_out;
    float* enc_out = out;                             // [B, T, H] (staging for xw0, final enc output)
    float* dec_final = out + (size_t)ENC_ELEMS;       // [B, PRED, OUT]

    float *hb, *hd, *part, *dout;
    cudaGetSymbolAddress((void**)&hb,   g_h);
    cudaGetSymbolAddress((void**)&hd,   g_hd);
    cudaGetSymbolAddress((void**)&part, g_part);
    cudaGetSymbolAddress((void**)&dout, g_decout);

    // zero all encoder hidden ping-pong buffers (initial h_{-1} = 0 for every parity)
    cudaMemsetAsync(hb, 0, (size_t)NLAYER*2*BH*sizeof(float), 0);

    // layer-0 input projection (includes bih0) staged into enc_out
    proj0_kernel<<<NT/32, 512>>>(x, eWih0, ebih, enc_out);

    // encoder wavefront: supersteps s = 0 .. SEQT+NLAYER-2
    dim3 wg(BATCH/128, HIDDEN/128, NLAYER);   // 8 x 4 x 4
    for (int s = 0; s < SEQT + NLAYER - 1; s++)
        wave_step<<<wg, 256>>>(s, eWih, eWhh, ebih, ebhh, hb, enc_out);

    // decoder: 10 steps x 4 layers, split-K partial + reduce
    dim3 dg(BATCH/128, HIDDEN/128, 4);        // 8 x 4 x 4
    for (int p = 0; p < PRED; p++) {
        float* hdcur  = hd + (size_t)(p & 1)*NLAYER*BH;
        float* hdprev = hd + (size_t)((p + 1) & 1)*NLAYER*BH;
        for (int l = 0; l < NLAYER; l++) {
            const float* xin = (l == 0)
                ? ((p == 0) ? hb + ((size_t)3*2 + 0)*BH          // h_{3,T-1} parity (127+3)&1=0
                            : hdprev + (size_t)3*BH)
                : hdcur + (size_t)(l-1)*BH;
            const float* hin = (p == 0)
                ? hb + ((size_t)l*2 + ((127 + l) & 1))*BH        // encoder final hidden of layer l
                : hdprev + (size_t)l*BH;
            dec_partial<<<dg, 256>>>(xin, dWih + (size_t)l*HH, hin, dWhh + (size_t)l*HH, part);
            dec_reduce<<<BH/4/256, 256>>>(part, dbih + l*HIDDEN, dbhh + l*HIDDEN,
                                          hdcur + (size_t)l*BH,
                                          (l == NLAYER-1) ? (dout + (size_t)p*HIDDEN) : nullptr);
        }
    }

    // final FC
    fc_kernel<<<BATCH*PRED/8, 256>>>(dout, fcW, fcb, dec_final);
}

// round 11
// speedup vs baseline: 2.4659x; 1.0949x over previous
#include <cuda_runtime.h>
#include <math.h>

#define BATCH 1024
#define SEQT 128
#define HIDDEN 512
#define HH (HIDDEN*HIDDEN)
#define BH (BATCH*HIDDEN)
#define NLAYER 4
#define PRED 10
#define INDIM 6
#define OUTDIM 6
#define NT (BATCH*SEQT)
#define ENC_ELEMS (NT*HIDDEN)
#define PADK 20

// ---------------- scratch (device globals; no allocation allowed) ----------------
__device__ float g_h[NLAYER*2*BH];            // encoder hidden ping-pong [layer][parity][B*H]
__device__ float g_hd[2*NLAYER*BH];           // decoder hidden ping-pong [parity][layer][B*H]
__device__ float g_part[4*BH];                // split-K partials
__device__ float g_decout[BATCH*PRED*HIDDEN]; // decoder outputs for FC

// ---------------- tf32 helpers ----------------
__device__ __forceinline__ unsigned cvt_tf32(float v){
    unsigned r; asm("cvt.rna.tf32.f32 %0, %1;" : "=r"(r) : "f"(v)); return r;
}
__device__ __forceinline__ void mma_tf32(float* d, const unsigned* a, const unsigned* b){
    asm volatile(
        "mma.sync.aligned.m16n8k8.row.col.f32.tf32.tf32.f32 "
        "{%0,%1,%2,%3}, {%4,%5,%6,%7}, {%8,%9}, {%0,%1,%2,%3};"
        : "+f"(d[0]), "+f"(d[1]), "+f"(d[2]), "+f"(d[3])
        : "r"(a[0]), "r"(a[1]), "r"(a[2]), "r"(a[3]), "r"(b[0]), "r"(b[1]));
}

// ---------------- MUFU-free tanh ----------------
__device__ __forceinline__ float fast_tanh(float x){
    float cx = fminf(fmaxf(x, -9.5f), 9.5f);
    float z  = cx * 2.8853900818f;               // 2x * log2(e)
    float y  = z + 12582912.0f;                  // round to nearest int
    int   n  = __float_as_int(y) - 0x4B400000;
    float f  = z - (y - 12582912.0f);            // [-0.5, 0.5]
    float t = 1.5252733e-05f;
    t = fmaf(t, f, 1.5403530e-04f);
    t = fmaf(t, f, 1.3333558e-03f);
    t = fmaf(t, f, 9.6181291e-03f);
    t = fmaf(t, f, 5.5504109e-02f);
    t = fmaf(t, f, 2.4022651e-01f);
    t = fmaf(t, f, 6.9314718e-01f);
    t = t * f;                                   // 2^f - 1
    float s   = __int_as_float((n + 127) << 23);
    float em1 = fmaf(s, t, s - 1.0f);            // e^{2x} - 1
    float ep1 = em1 + 2.0f;
    float r = __int_as_float(0x7EF311C3 - __float_as_int(ep1));
    r = r * fmaf(-ep1, r, 2.0f);
    r = r * fmaf(-ep1, r, 2.0f);
    r = r * fmaf(-ep1, r, 2.0f);
    return em1 * r;
}

// ---------------- tf32 tensor-core GEMM pass (512 threads, 16 warps) ----------------
// acc += A[bm:bm+128, kb:ke] @ W[bn:bn+128, kb:ke]^T   (both row-major [*, 512])
// 16 warps in 4x4 grid; warp tile 32(M) x 32(N): 2 m16 x 4 n8 MMAs per k8.
// Per chunk: LDG c+1 -> 32 frag LDS -> sync -> MMA h0 -> STS c+1 -> MMA h1 -> sync.
__device__ __forceinline__ void gemm_tf32(
    const float* __restrict__ A, const float* __restrict__ W,
    int kb, int ke, int bm, int bn, int tid,
    unsigned (*As)[PADK], unsigned (*Ws)[PADK], float (*d)[4][4])
{
    int rowL = tid >> 2;              // 0..127
    int koff = (tid & 3) << 2;        // 0,4,8,12
    int lane = tid & 31;
    int q = lane >> 2, r = lane & 3;
    int wid = tid >> 5;               // 0..15
    int wm = (wid & 3) * 32;
    int wn = (wid >> 2) * 32;

    const float* Ag = A + (size_t)(bm + rowL)*HIDDEN + koff;
    const float* Wg = W + (size_t)(bn + rowL)*HIDDEN + koff;

    float4 a0 = *(const float4*)(Ag + kb);
    float4 w0 = *(const float4*)(Wg + kb);

#define STS_CHUNK() do { \
    As[rowL][koff+0]=cvt_tf32(a0.x); As[rowL][koff+1]=cvt_tf32(a0.y); \
    As[rowL][koff+2]=cvt_tf32(a0.z); As[rowL][koff+3]=cvt_tf32(a0.w); \
    Ws[rowL][koff+0]=cvt_tf32(w0.x); Ws[rowL][koff+1]=cvt_tf32(w0.y); \
    Ws[rowL][koff+2]=cvt_tf32(w0.z); Ws[rowL][koff+3]=cvt_tf32(w0.w); \
} while(0)

    STS_CHUNK();
    __syncthreads();

    for (int k0 = kb; k0 < ke; k0 += 16) {
        bool more = (k0 + 16 < ke);
        if (more) {                     // gmem prefetch chunk c+1
            a0 = *(const float4*)(Ag + k0 + 16);
            w0 = *(const float4*)(Wg + k0 + 16);
        }
        // load all fragments of current chunk (both k8 halves) into registers
        unsigned bf[2][4][2], af[2][2][4];
        #pragma unroll
        for (int h = 0; h < 2; h++) {
            int s8 = h * 8;
            #pragma unroll
            for (int j = 0; j < 4; j++) {
                bf[h][j][0] = Ws[wn + 8*j + q][s8 + r];
                bf[h][j][1] = Ws[wn + 8*j + q][s8 + 4 + r];
            }
            #pragma unroll
            for (int t = 0; t < 2; t++) {
                af[h][t][0] = As[wm + 16*t + q][s8 + r];
                af[h][t][1] = As[wm + 16*t + 8 + q][s8 + r];
                af[h][t][2] = As[wm + 16*t + q][s8 + 4 + r];
                af[h][t][3] = As[wm + 16*t + 8 + q][s8 + 4 + r];
            }
        }
        __syncthreads();                // all warps done reading smem
        #pragma unroll
        for (int t = 0; t < 2; t++)     // MMA half 0 — overlaps peers' STS
            #pragma unroll
            for (int j = 0; j < 4; j++)
                mma_tf32(d[t][j], af[0][t], bf[0][j]);
        if (more) STS_CHUNK();          // refill smem while tensor pipe busy
        #pragma unroll
        for (int t = 0; t < 2; t++)     // MMA half 1
            #pragma unroll
            for (int j = 0; j < 4; j++)
                mma_tf32(d[t][j], af[1][t], bf[1][j]);
        __syncthreads();                // STS visible before next frag loads
    }
#undef STS_CHUNK
}

// ---------------- layer-0 projection: [NT,6] @ [512,6]^T + bih0 -> enc_out region ----------------
__global__ void __launch_bounds__(512) proj0_kernel(const float* __restrict__ x,
    const float* __restrict__ W, const float* __restrict__ bias, float* __restrict__ out)
{
    __shared__ float Ws[HIDDEN*INDIM];
    __shared__ float bs[HIDDEN];
    __shared__ float xs[32][INDIM];
    int tid = threadIdx.x;
    for (int i = tid; i < HIDDEN*INDIM; i += 512) Ws[i] = W[i];
    if (tid < HIDDEN) bs[tid] = bias[tid];
    int r0 = blockIdx.x * 32;
    if (tid < 32*INDIM) xs[tid/INDIM][tid%INDIM] = x[(size_t)(r0 + tid/INDIM)*INDIM + tid%INDIM];
    __syncthreads();
    int h = tid;
    #pragma unroll 4
    for (int r = 0; r < 32; r++) {
        float acc = bs[h];
        #pragma unroll
        for (int d = 0; d < INDIM; d++) acc += xs[r][d] * Ws[h*INDIM + d];
        out[(size_t)(r0 + r)*HIDDEN + h] = acc;
    }
}

// ---------------- encoder wavefront superstep (tf32 tensor core, 512 thr) ----------------
// blockIdx.z = layer l; computes ts = s - l.
__global__ void __launch_bounds__(512, 1) wave_step(
    int s,
    const float* __restrict__ eWih, const float* __restrict__ eWhh,
    const float* __restrict__ ebih, const float* __restrict__ ebhh,
    float* __restrict__ hb, float* __restrict__ enc_out)
{
    int l = blockIdx.z;
    int ts = s - l;
    if (ts < 0 || ts >= SEQT) return;
    int p_r = (s + 1) & 1, p_w = s & 1;

    __shared__ __align__(16) unsigned As[128][PADK];
    __shared__ __align__(16) unsigned Ws[128][PADK];
    int tid = threadIdx.x;
    int bm = blockIdx.x * 128, bn = blockIdx.y * 128;

    float d[2][4][4];
    #pragma unroll
    for (int t = 0; t < 2; t++)
        #pragma unroll
        for (int j = 0; j < 4; j++)
            #pragma unroll
            for (int c = 0; c < 4; c++) d[t][j][c] = 0.f;

    if (l == 0) {
        gemm_tf32(hb + (size_t)p_r*BH, eWhh, 0, HIDDEN, bm, bn, tid, As, Ws, d);
    } else {
        gemm_tf32(hb + ((size_t)(l-1)*2 + p_r)*BH, eWih + (size_t)(l-1)*HH, 0, HIDDEN, bm, bn, tid, As, Ws, d);
        gemm_tf32(hb + ((size_t)l*2 + p_r)*BH,     eWhh + (size_t)l*HH,     0, HIDDEN, bm, bn, tid, As, Ws, d);
    }

    int lane = tid & 31;
    int q = lane >> 2, r = lane & 3;
    int wid = tid >> 5;
    int wm = (wid & 3) * 32;
    int wn = (wid >> 2) * 32;
    float* hout = hb + ((size_t)l*2 + p_w)*BH;

    #pragma unroll
    for (int j = 0; j < 4; j++) {
        int c = bn + wn + 8*j + 2*r;
        float b0 = ebhh[l*HIDDEN + c], b1 = ebhh[l*HIDDEN + c + 1];
        if (l > 0) { b0 += ebih[l*HIDDEN + c]; b1 += ebih[l*HIDDEN + c + 1]; }
        #pragma unroll
        for (int t = 0; t < 2; t++) {
            int ra = bm + wm + 16*t + q;
            int rb = ra + 8;
            float v0 = d[t][j][0] + b0, v1 = d[t][j][1] + b1;
            float v2 = d[t][j][2] + b0, v3 = d[t][j][3] + b1;
            if (l == 0) {
                const float* xa = enc_out + ((size_t)ra*SEQT + ts)*HIDDEN + c;
                const float* xb = enc_out + ((size_t)rb*SEQT + ts)*HIDDEN + c;
                float2 pa = *(const float2*)xa;
                float2 pb = *(const float2*)xb;
                v0 += pa.x; v1 += pa.y; v2 += pb.x; v3 += pb.y;
            }
            v0 = fast_tanh(v0); v1 = fast_tanh(v1);
            v2 = fast_tanh(v2); v3 = fast_tanh(v3);
            *(float2*)(hout + (size_t)ra*HIDDEN + c) = make_float2(v0, v1);
            *(float2*)(hout + (size_t)rb*HIDDEN + c) = make_float2(v2, v3);
            if (l == 3) {
                *(float2*)(enc_out + ((size_t)ra*SEQT + ts)*HIDDEN + c) = make_float2(v0, v1);
                *(float2*)(enc_out + ((size_t)rb*SEQT + ts)*HIDDEN + c) = make_float2(v2, v3);
            }
        }
    }
}

// ---------------- decoder split-K partial (tf32, 512 thr) ----------------
__global__ void __launch_bounds__(512, 1) dec_partial(
    const float* __restrict__ xin, const float* __restrict__ Wih,
    const float* __restrict__ hin, const float* __restrict__ Whh,
    float* __restrict__ part)
{
    __shared__ __align__(16) unsigned As[128][PADK];
    __shared__ __align__(16) unsigned Ws[128][PADK];
    int tid = threadIdx.x;
    int bm = blockIdx.x * 128, bn = blockIdx.y * 128;
    int z = blockIdx.z;

    float d[2][4][4];
    #pragma unroll
    for (int t = 0; t < 2; t++)
        #pragma unroll
        for (int j = 0; j < 4; j++)
            #pragma unroll
            for (int c = 0; c < 4; c++) d[t][j][c] = 0.f;

    const float* A = (z >> 1) ? hin : xin;
    const float* W = (z >> 1) ? Whh : Wih;
    int kb = (z & 1) * 256;
    gemm_tf32(A, W, kb, kb + 256, bm, bn, tid, As, Ws, d);

    int lane = tid & 31;
    int q = lane >> 2, r = lane & 3;
    int wid = tid >> 5;
    int wm = (wid & 3) * 32;
    int wn = (wid >> 2) * 32;
    float* dst = part + (size_t)z*BH;

    #pragma unroll
    for (int j = 0; j < 4; j++) {
        int c = bn + wn + 8*j + 2*r;
        #pragma unroll
        for (int t = 0; t < 2; t++) {
            int ra = bm + wm + 16*t + q;
            int rb = ra + 8;
            *(float2*)(dst + (size_t)ra*HIDDEN + c) = make_float2(d[t][j][0], d[t][j][1]);
            *(float2*)(dst + (size_t)rb*HIDDEN + c) = make_float2(d[t][j][2], d[t][j][3]);
        }
    }
}

// ---------------- decoder reduce: h = tanh(sum parts + bih + bhh) ----------------
__global__ void __launch_bounds__(256) dec_reduce(
    const float* __restrict__ part, const float* __restrict__ bih, const float* __restrict__ bhh,
    float* __restrict__ hout, float* __restrict__ dout)
{
    int e = blockIdx.x * blockDim.x + threadIdx.x;   // float4 index over BH/4
    int n = (e & 127) * 4;
    int m = e >> 7;
    size_t off = (size_t)e * 4;
    float4 s0 = *(const float4*)(part + off);
    float4 s1 = *(const float4*)(part + BH + off);
    float4 s2 = *(const float4*)(part + 2*(size_t)BH + off);
    float4 s3 = *(const float4*)(part + 3*(size_t)BH + off);
    float4 b1 = *(const float4*)(bih + n);
    float4 b2 = *(const float4*)(bhh + n);
    float4 v;
    v.x = fast_tanh(s0.x + s1.x + s2.x + s3.x + b1.x + b2.x);
    v.y = fast_tanh(s0.y + s1.y + s2.y + s3.y + b1.y + b2.y);
    v.z = fast_tanh(s0.z + s1.z + s2.z + s3.z + b1.z + b2.z);
    v.w = fast_tanh(s0.w + s1.w + s2.w + s3.w + b1.w + b2.w);
    *(float4*)(hout + off) = v;
    if (dout) *(float4*)(dout + (size_t)m*PRED*HIDDEN + n) = v;
}

// ---------------- final FC: [B*PRED,512] @ [6,512]^T + b ----------------
__global__ void __launch_bounds__(256) fc_kernel(const float* __restrict__ X,
    const float* __restrict__ W, const float* __restrict__ bias, float* __restrict__ out)
{
    __shared__ float Ws[OUTDIM][HIDDEN];
    int tid = threadIdx.x;
    for (int i = tid; i < OUTDIM*HIDDEN; i += 256) Ws[i/HIDDEN][i%HIDDEN] = W[i];
    __syncthreads();
    int warp = tid >> 5, lane = tid & 31;
    int row = blockIdx.x*8 + warp;
    float s[OUTDIM];
    #pragma unroll
    for (int o = 0; o < OUTDIM; o++) s[o] = 0.f;
    for (int k = lane; k < HIDDEN; k += 32) {
        float xv = X[(size_t)row*HIDDEN + k];
        #pragma unroll
        for (int o = 0; o < OUTDIM; o++) s[o] += xv * Ws[o][k];
    }
    #pragma unroll
    for (int o = 0; o < OUTDIM; o++) {
        #pragma unroll
        for (int off = 16; off; off >>= 1) s[o] += __shfl_down_sync(0xffffffffu, s[o], off);
    }
    if (lane == 0) {
        #pragma unroll
        for (int o = 0; o < OUTDIM; o++) out[(size_t)row*OUTDIM + o] = s[o] + bias[o];
    }
}

extern "C" void kernel_launch(void* const* d_in, const int* in_sizes, int n_in,
                              void* d_out, int out_size)
{
    (void)in_sizes; (void)n_in; (void)out_size;
    const float* x     = (const float*)d_in[0];
    const float* eWih0 = (const float*)d_in[1];
    const float* eWih  = (const float*)d_in[2];
    const float* eWhh  = (const float*)d_in[3];
    const float* ebih  = (const float*)d_in[4];
    const float* ebhh  = (const float*)d_in[5];
    const float* dWih  = (const float*)d_in[6];
    const float* dWhh  = (const float*)d_in[7];
    const float* dbih  = (const float*)d_in[8];
    const float* dbhh  = (const float*)d_in[9];
    const float* fcW   = (const float*)d_in[10];
    const float* fcb   = (const float*)d_in[11];

    float* out = (float*)d_out;
    float* enc_out = out;                             // [B, T, H] (staging for xw0, final enc output)
    float* dec_final = out + (size_t)ENC_ELEMS;       // [B, PRED, OUT]

    float *hb, *hd, *part, *dout;
    cudaGetSymbolAddress((void**)&hb,   g_h);
    cudaGetSymbolAddress((void**)&hd,   g_hd);
    cudaGetSymbolAddress((void**)&part, g_part);
    cudaGetSymbolAddress((void**)&dout, g_decout);

    // zero all encoder hidden ping-pong buffers (initial h_{-1} = 0 for every parity)
    cudaMemsetAsync(hb, 0, (size_t)NLAYER*2*BH*sizeof(float), 0);

    // layer-0 input projection (includes bih0) staged into enc_out
    proj0_kernel<<<NT/32, 512>>>(x, eWih0, ebih, enc_out);

    // encoder wavefront: supersteps s = 0 .. SEQT+NLAYER-2
    dim3 wg(BATCH/128, HIDDEN/128, NLAYER);   // 8 x 4 x 4
    for (int s = 0; s < SEQT + NLAYER - 1; s++)
        wave_step<<<wg, 512>>>(s, eWih, eWhh, ebih, ebhh, hb, enc_out);

    // decoder: 10 steps x 4 layers, split-K partial + reduce
    dim3 dg(BATCH/128, HIDDEN/128, 4);        // 8 x 4 x 4
    for (int p = 0; p < PRED; p++) {
        float* hdcur  = hd + (size_t)(p & 1)*NLAYER*BH;
        float* hdprev = hd + (size_t)((p + 1) & 1)*NLAYER*BH;
        for (int l = 0; l < NLAYER; l++) {
            const float* xin = (l == 0)
                ? ((p == 0) ? hb + ((size_t)3*2 + 0)*BH          // h_{3,T-1} parity (127+3)&1=0
                            : hdprev + (size_t)3*BH)
                : hdcur + (size_t)(l-1)*BH;
            const float* hin = (p == 0)
                ? hb + ((size_t)l*2 + ((127 + l) & 1))*BH        // encoder final hidden of layer l
                : hdprev + (size_t)l*BH;
            dec_partial<<<dg, 512>>>(xin, dWih + (size_t)l*HH, hin, dWhh + (size_t)l*HH, part);
            dec_reduce<<<BH/4/256, 256>>>(part, dbih + l*HIDDEN, dbhh + l*HIDDEN,
                                          hdcur + (size_t)l*BH,
                                          (l == NLAYER-1) ? (dout + (size_t)p*HIDDEN) : nullptr);
        }
    }

    // final FC
    fc_kernel<<<BATCH*PRED/8, 256>>>(dout, fcW, fcb, dec_final);
}